// round 13
// baseline (speedup 1.0000x reference)
#include <cuda_runtime.h>
#include <cstdint>
#include <math.h>

// ---------------- constants ----------------
#define NPOS_TOTAL 33600     // 25600 + 6400 + 1600
#define NCAND      3000
#define NWORDS     47        // ceil(3000/64)
#define KTOP       1000

// ---------------- device scratch (no allocation allowed) ----------------
__device__ float              g_score[NPOS_TOTAL];
__device__ int                g_label[NPOS_TOTAL];
__device__ float              g_box[NPOS_TOTAL * 4];
__device__ float              c_score[NCAND];
__device__ int                c_label[NCAND];
__device__ float              c_box[NCAND * 4];
__device__ int                g_order[NCAND];
__device__ float              g_sbox[NCAND * 4];
__device__ int                g_valid[NCAND];
__device__ unsigned long long g_mask[NCAND * NWORDS];
__device__ int                g_keep[NCAND];

__device__ __forceinline__ unsigned int fflip(float f) {
    unsigned int u = __float_as_uint(f);
    return (u & 0x80000000u) ? ~u : (u | 0x80000000u);
}

// XLA:GPU lowering of exp = libdevice __nv_expf = CUDA expf (no fast-math).
// logistic expander: 1 / (1 + exp(-x)) with rn add + rn divide.
__device__ __forceinline__ float sigm(float x) {
    return __fdiv_rn(1.0f, __fadd_rn(1.0f, expf(-x)));
}

// ================= Stage A: head conv + decode =================
// Reference stack model (jax / XLA on the GB300 GPU, fp32):
//   obj (1x256 dot)  -> strength-reduced to reduce(multiply(...)):
//                       lane l partial = sum_j  UNFUSED  w[l+32j]*x[l+32j]  (j asc)
//                       then warp shfl_down tree: offsets 16,8,4,2,1
//   cls (80x256), reg (4x256) -> cublas sgemm: k-sequential FUSED FMA  (as before)
__global__ __launch_bounds__(256) void head_kernel(
    const float* __restrict__ feat,
    const float* __restrict__ Wobj, const float* __restrict__ bobj,
    const float* __restrict__ Wcls, const float* __restrict__ bcls,
    const float* __restrict__ Wreg, const float* __restrict__ breg,
    int H, int W, float stride, int out_off)
{
    __shared__ __align__(16) float sm[85 * 128];
    const int HW   = H * W;
    const int p0   = blockIdx.x * 128;
    const int tid  = threadIdx.x;
    const int wid  = tid >> 5;
    const int lane = tid & 31;
    const int nout = (92 - wid) / 8;

    float acc[11][4];
    #pragma unroll
    for (int j = 0; j < 11; j++)
        #pragma unroll
        for (int k = 0; k < 4; k++) acc[j][k] = 0.0f;

    // obj lane-partials: warp w owns positions [w*16, w*16+16)
    float objp[16];
    #pragma unroll
    for (int q = 0; q < 16; q++) objp[q] = 0.0f;

    const float* wptr[11];
    #pragma unroll
    for (int j = 0; j < 11; j++) {
        int o = wid + 8 * j;
        if (o < 85)
            wptr[j] = (o == 0) ? Wobj : (o < 5 ? Wreg + (o - 1) * 256 : Wcls + (o - 5) * 256);
        else
            wptr[j] = Wobj;
    }

    float4* xs4 = (float4*)sm;
    for (int ch = 0; ch < 4; ch++) {
        int c0 = ch * 64;
        __syncthreads();
        for (int idx = tid; idx < 64 * 128; idx += 256) {
            int c = idx >> 7, p = idx & 127;
            int pg = p0 + p;
            sm[idx] = (pg < HW) ? feat[(size_t)(c0 + c) * HW + pg] : 0.0f;
        }
        __syncthreads();
        // ---- obj: per-lane stride-32 partials, unfused mul+add, c ascending ----
        {
            float wl0 = Wobj[c0 + lane];
            float wl1 = Wobj[c0 + 32 + lane];
            int qbase = wid * 16;
            #pragma unroll
            for (int q = 0; q < 16; q++) {
                float x0 = sm[lane * 128 + qbase + q];
                float x1 = sm[(lane + 32) * 128 + qbase + q];
                objp[q] = __fadd_rn(objp[q], __fmul_rn(wl0, x0));
                objp[q] = __fadd_rn(objp[q], __fmul_rn(wl1, x1));
            }
        }
        // ---- cls/reg: fused sequential-k (skip the obj slot: wid==0, j==0) ----
        #pragma unroll
        for (int j = 0; j < 11; j++) {
            if (j >= nout) break;
            if (j == 0 && wid == 0) continue;     // obj handled above
            const float* wp = wptr[j] + c0;
            float a0 = acc[j][0], a1 = acc[j][1], a2 = acc[j][2], a3 = acc[j][3];
            #pragma unroll
            for (int c = 0; c < 64; c += 4) {
                float4 wv = *(const float4*)(wp + c);
                float4 x0 = xs4[(c + 0) * 32 + lane];
                float4 x1 = xs4[(c + 1) * 32 + lane];
                float4 x2 = xs4[(c + 2) * 32 + lane];
                float4 x3 = xs4[(c + 3) * 32 + lane];
                a0 = __fmaf_rn(wv.x, x0.x, a0); a1 = __fmaf_rn(wv.x, x0.y, a1);
                a2 = __fmaf_rn(wv.x, x0.z, a2); a3 = __fmaf_rn(wv.x, x0.w, a3);
                a0 = __fmaf_rn(wv.y, x1.x, a0); a1 = __fmaf_rn(wv.y, x1.y, a1);
                a2 = __fmaf_rn(wv.y, x1.z, a2); a3 = __fmaf_rn(wv.y, x1.w, a3);
                a0 = __fmaf_rn(wv.z, x2.x, a0); a1 = __fmaf_rn(wv.z, x2.y, a1);
                a2 = __fmaf_rn(wv.z, x2.z, a2); a3 = __fmaf_rn(wv.z, x2.w, a3);
                a0 = __fmaf_rn(wv.w, x3.x, a0); a1 = __fmaf_rn(wv.w, x3.y, a1);
                a2 = __fmaf_rn(wv.w, x3.z, a2); a3 = __fmaf_rn(wv.w, x3.w, a3);
            }
            acc[j][0] = a0; acc[j][1] = a1; acc[j][2] = a2; acc[j][3] = a3;
        }
    }
    // ---- obj warp tree reduce: shfl_down offsets 16,8,4,2,1 (XLA order) ----
    float objv[16];
    #pragma unroll
    for (int q = 0; q < 16; q++) {
        float v = objp[q];
        v = __fadd_rn(v, __shfl_down_sync(0xffffffffu, v, 16));
        v = __fadd_rn(v, __shfl_down_sync(0xffffffffu, v, 8));
        v = __fadd_rn(v, __shfl_down_sync(0xffffffffu, v, 4));
        v = __fadd_rn(v, __shfl_down_sync(0xffffffffu, v, 2));
        v = __fadd_rn(v, __shfl_down_sync(0xffffffffu, v, 1));
        objv[q] = v;                               // valid on lane 0
    }
    __syncthreads();
    // scatter outputs (+bias) into sm as y[o][p]
    #pragma unroll
    for (int j = 0; j < 11; j++) {
        if (j >= nout) break;
        int o = wid + 8 * j;
        if (o == 0) continue;                      // obj written below
        float b = (o < 5) ? breg[o - 1] : bcls[o - 5];
        #pragma unroll
        for (int k = 0; k < 4; k++) sm[o * 128 + lane * 4 + k] = __fadd_rn(acc[j][k], b);
    }
    if (lane == 0) {
        float b = bobj[0];
        #pragma unroll
        for (int q = 0; q < 16; q++)
            sm[0 * 128 + wid * 16 + q] = __fadd_rn(objv[q], b);
    }
    __syncthreads();

    if (tid < 128) {
        int pg = p0 + tid;
        if (pg < HW) {
            float so = sigm(sm[0 * 128 + tid]);
            float r0 = __fmul_rn(expf(sm[1 * 128 + tid]), stride);
            float r1 = __fmul_rn(expf(sm[2 * 128 + tid]), stride);
            float r2 = __fmul_rn(expf(sm[3 * 128 + tid]), stride);
            float r3 = __fmul_rn(expf(sm[4 * 128 + tid]), stride);
            float mx = -1.0f;
            int lab = 0;
            for (int c = 0; c < 80; c++) {
                float pc = __fmul_rn(so, sigm(sm[(5 + c) * 128 + tid]));
                if (pc > mx) { mx = pc; lab = c; }
            }
            float ax = __fmul_rn(__fadd_rn((float)(pg % W), 0.5f), stride);
            float ay = __fmul_rn(__fadd_rn((float)(pg / W), 0.5f), stride);
            int gi = out_off + pg;
            g_score[gi] = mx;
            g_label[gi] = lab;
            g_box[gi * 4 + 0] = __fsub_rn(ax, r0);
            g_box[gi * 4 + 1] = __fsub_rn(ay, r1);
            g_box[gi * 4 + 2] = __fadd_rn(ax, r2);
            g_box[gi * 4 + 3] = __fadd_rn(ay, r3);
        }
    }
}

// ================= Stage B: per-level exact top-1000, stable low-first =================
__global__ __launch_bounds__(1024) void topk_kernel() {
    __shared__ unsigned int hist[256];
    __shared__ unsigned long long skeys[2048];
    __shared__ unsigned int s_prefix, s_K, s_cnt;

    const int loff[3] = {0, 25600, 32000};
    const int lnum[3] = {25600, 6400, 1600};
    int l = blockIdx.x;
    int off = loff[l], n = lnum[l];
    int tid = threadIdx.x;

    unsigned int prefix = 0;
    int K = KTOP;
    for (int pass = 0; pass < 4; pass++) {
        int shift = 24 - 8 * pass;
        if (tid < 256) hist[tid] = 0;
        __syncthreads();
        for (int i = tid; i < n; i += 1024) {
            unsigned int k = fflip(g_score[off + i]);
            bool ok = (pass == 0) || ((k >> (shift + 8)) == (prefix >> (shift + 8)));
            if (ok) atomicAdd(&hist[(k >> shift) & 255u], 1u);
        }
        __syncthreads();
        if (tid == 0) {
            int cum = 0, b = 255;
            for (; b > 0; b--) {
                int h = (int)hist[b];
                if (cum + h >= K) break;
                cum += h;
            }
            s_prefix = prefix | ((unsigned int)b << shift);
            s_K = (unsigned int)(K - cum);
        }
        __syncthreads();
        prefix = s_prefix;
        K = (int)s_K;
        __syncthreads();
    }
    unsigned int T = prefix;

    if (tid == 0) s_cnt = 0;
    __syncthreads();
    for (int i = tid; i < n; i += 1024) {
        unsigned int k = fflip(g_score[off + i]);
        if (k >= T) {
            unsigned int p = atomicAdd(&s_cnt, 1u);
            if (p < 2048)
                skeys[p] = ((unsigned long long)k << 32) | (unsigned int)(~i);
        }
    }
    __syncthreads();
    unsigned int cnt = min(s_cnt, 2048u);
    for (int i = tid; i < 2048; i += 1024)
        if ((unsigned)i >= cnt) skeys[i] = 0ull;
    __syncthreads();

    for (int k2 = 2; k2 <= 2048; k2 <<= 1) {
        for (int j = k2 >> 1; j > 0; j >>= 1) {
            for (int idx = tid; idx < 2048; idx += 1024) {
                int ixj = idx ^ j;
                if (ixj > idx) {
                    unsigned long long a = skeys[idx], b = skeys[ixj];
                    bool desc = ((idx & k2) == 0);
                    if (desc ? (a < b) : (a > b)) { skeys[idx] = b; skeys[ixj] = a; }
                }
            }
            __syncthreads();
        }
    }

    for (int r = tid; r < KTOP; r += 1024) {
        unsigned long long key = skeys[r];
        int hw = (int)(~(unsigned int)key);
        int gi = off + hw;
        int ci = l * KTOP + r;
        c_score[ci] = g_score[gi];
        c_label[ci] = g_label[gi];
        #pragma unroll
        for (int k = 0; k < 4; k++) c_box[ci * 4 + k] = g_box[gi * 4 + k];
    }
}

// ================= Stage C: global argsort(-score), stable =================
__global__ __launch_bounds__(1024) void gsort_kernel() {
    __shared__ unsigned long long sk[4096];
    int tid = threadIdx.x;
    for (int i = tid; i < 4096; i += 1024)
        sk[i] = (i < NCAND)
              ? (((unsigned long long)fflip(c_score[i]) << 32) | (unsigned int)(~i))
              : 0ull;
    __syncthreads();
    for (int k2 = 2; k2 <= 4096; k2 <<= 1) {
        for (int j = k2 >> 1; j > 0; j >>= 1) {
            for (int idx = tid; idx < 4096; idx += 1024) {
                int ixj = idx ^ j;
                if (ixj > idx) {
                    unsigned long long a = sk[idx], b = sk[ixj];
                    bool desc = ((idx & k2) == 0);
                    if (desc ? (a < b) : (a > b)) { sk[idx] = b; sk[ixj] = a; }
                }
            }
            __syncthreads();
        }
    }
    for (int i = tid; i < NCAND; i += 1024) {
        int ci = (int)(~(unsigned int)sk[i]);
        g_order[i] = ci;
        float offv = __fmul_rn((float)c_label[ci], 8192.0f);
        #pragma unroll
        for (int k = 0; k < 4; k++)
            g_sbox[i * 4 + k] = __fadd_rn(c_box[ci * 4 + k], offv);
        g_valid[i] = (c_score[ci] >= 0.05f) ? 1 : 0;
    }
}

// ================= Stage D1: IoU bitmask =================
__global__ __launch_bounds__(64) void nms_mask_kernel() {
    __shared__ float4 bj[64];
    __shared__ float  aj[64];
    int t = threadIdx.x;
    int ib = blockIdx.x * 64, jb = blockIdx.y * 64;
    int j = jb + t;
    if (j < NCAND) {
        float4 b = *(const float4*)&g_sbox[j * 4];
        bj[t] = b;
        aj[t] = __fmul_rn(__fsub_rn(b.z, b.x), __fsub_rn(b.w, b.y));
    }
    __syncthreads();
    int i = ib + t;
    if (i >= NCAND) return;
    float4 a = *(const float4*)&g_sbox[i * 4];
    float areai = __fmul_rn(__fsub_rn(a.z, a.x), __fsub_rn(a.w, a.y));
    unsigned long long bits = 0ull;
    int jn = min(64, NCAND - jb);
    for (int jj = 0; jj < jn; jj++) {
        float4 b = bj[jj];
        float xx1 = fmaxf(a.x, b.x), yy1 = fmaxf(a.y, b.y);
        float xx2 = fminf(a.z, b.z), yy2 = fminf(a.w, b.w);
        float w = fmaxf(1e-10f, __fsub_rn(xx2, xx1));
        float h = fmaxf(1e-10f, __fsub_rn(yy2, yy1));
        float inter = __fmul_rn(w, h);
        float denom = __fadd_rn(__fsub_rn(__fadd_rn(areai, aj[jj]), inter), 1e-14f);
        float iou = __fdiv_rn(inter, denom);
        if (iou > 0.6f) bits |= (1ull << jj);
    }
    g_mask[(size_t)i * NWORDS + blockIdx.y] = bits;
}

// ================= Stage D2: exact greedy pass, 64-grouped =================
__global__ __launch_bounds__(256) void nms_seq_kernel() {
    __shared__ unsigned long long remv[NWORDS];
    __shared__ unsigned long long srows[64 * NWORDS];
    __shared__ unsigned char skp[64];
    int tid = threadIdx.x;
    if (tid < NWORDS) remv[tid] = 0ull;

    for (int g = 0; g < NWORDS; g++) {
        __syncthreads();
        int ib = g * 64;
        int cnt = min(64, NCAND - ib);
        for (int idx = tid; idx < cnt * NWORDS; idx += 256)
            srows[idx] = g_mask[(size_t)ib * NWORDS + idx];
        __syncthreads();
        if (tid == 0) {
            unsigned long long r = remv[g];
            for (int li = 0; li < cnt; li++) {
                bool kp = g_valid[ib + li] && !((r >> li) & 1ull);
                skp[li] = kp ? 1 : 0;
                if (kp) r |= srows[li * NWORDS + g];
            }
            remv[g] = r;
        }
        __syncthreads();
        for (int t = tid; t < NWORDS * 4; t += 256) {
            int w = t % NWORDS, part = t / NWORDS;
            unsigned long long acc = 0ull;
            for (int li = part; li < cnt; li += 4)
                if (skp[li]) acc |= srows[li * NWORDS + w];
            if (acc) atomicOr(&remv[w], acc);
        }
        if (tid < cnt) g_keep[g_order[ib + tid]] = skp[tid];
    }
}

// ================= Stage E: write packed output =================
__global__ __launch_bounds__(256) void output_kernel(float* __restrict__ out, int out_size) {
    int i = blockIdx.x * 256 + threadIdx.x;
    if (i >= NCAND) return;
    #pragma unroll
    for (int k = 0; k < 4; k++) {
        int oi = i * 4 + k;
        if (oi < out_size) {
            float v = __fdiv_rn(c_box[i * 4 + k], 1280.0f);
            out[oi] = fminf(fmaxf(v, 0.0f), 1.0f);
        }
    }
    if (12000 + i < out_size) out[12000 + i] = c_score[i];
    if (15000 + i < out_size) out[15000 + i] = (float)c_label[i];
    if (18000 + i < out_size) out[18000 + i] = g_keep[i] ? 1.0f : 0.0f;
}

// ================= launch =================
extern "C" void kernel_launch(void* const* d_in, const int* in_sizes, int n_in,
                              void* d_out, int out_size) {
    (void)n_in;
    bool sig = (in_sizes[1] > 100000);
    const float *feat[3], *Wo[3], *bo[3], *Wc[3], *bc[3], *Wr[3], *br[3];
    for (int l = 0; l < 3; l++) {
        if (sig) {
            feat[l] = (const float*)d_in[l];
            Wo[l] = (const float*)d_in[3 + 6 * l + 0];
            bo[l] = (const float*)d_in[3 + 6 * l + 1];
            Wc[l] = (const float*)d_in[3 + 6 * l + 2];
            bc[l] = (const float*)d_in[3 + 6 * l + 3];
            Wr[l] = (const float*)d_in[3 + 6 * l + 4];
            br[l] = (const float*)d_in[3 + 6 * l + 5];
        } else {
            feat[l] = (const float*)d_in[7 * l + 0];
            Wo[l] = (const float*)d_in[7 * l + 1];
            bo[l] = (const float*)d_in[7 * l + 2];
            Wc[l] = (const float*)d_in[7 * l + 3];
            bc[l] = (const float*)d_in[7 * l + 4];
            Wr[l] = (const float*)d_in[7 * l + 5];
            br[l] = (const float*)d_in[7 * l + 6];
        }
    }
    const int   Hs[3]  = {160, 80, 40};
    const int   Ws[3]  = {160, 80, 40};
    const float st[3]  = {8.0f, 16.0f, 32.0f};
    const int   off[3] = {0, 25600, 32000};

    for (int l = 0; l < 3; l++) {
        int HW = Hs[l] * Ws[l];
        int nb = (HW + 127) / 128;
        head_kernel<<<nb, 256>>>(feat[l], Wo[l], bo[l], Wc[l], bc[l], Wr[l], br[l],
                                 Hs[l], Ws[l], st[l], off[l]);
    }
    topk_kernel<<<3, 1024>>>();
    gsort_kernel<<<1, 1024>>>();
    nms_mask_kernel<<<dim3(NWORDS, NWORDS), 64>>>();
    nms_seq_kernel<<<1, 256>>>();
    output_kernel<<<(NCAND + 255) / 256, 256>>>((float*)d_out, out_size);
}

// round 15
// speedup vs baseline: 1.0971x; 1.0971x over previous
#include <cuda_runtime.h>
#include <cstdint>
#include <math.h>

// ---------------- constants ----------------
#define NPOS_TOTAL 33600     // 25600 + 6400 + 1600
#define NCAND      3000
#define NWORDS     47        // ceil(3000/64)
#define KTOP       1000
#define ROWF       132       // padded tile row (floats): kills obj bank conflicts

// ---------------- device scratch (no allocation allowed) ----------------
__device__ float              g_score[NPOS_TOTAL];
__device__ int                g_label[NPOS_TOTAL];
__device__ float              g_box[NPOS_TOTAL * 4];
__device__ float              c_score[NCAND];
__device__ int                c_label[NCAND];
__device__ float              c_box[NCAND * 4];
__device__ int                g_order[NCAND];
__device__ float              g_sbox[NCAND * 4];
__device__ int                g_valid[NCAND];
__device__ unsigned long long g_mask[NCAND * NWORDS];
__device__ int                g_keep[NCAND];

__device__ __forceinline__ unsigned int fflip(float f) {
    unsigned int u = __float_as_uint(f);
    return (u & 0x80000000u) ? ~u : (u | 0x80000000u);
}

// XLA:GPU lowering of exp = libdevice __nv_expf = CUDA expf (no fast-math).
__device__ __forceinline__ float sigm(float x) {
    return __fdiv_rn(1.0f, __fadd_rn(1.0f, expf(-x)));
}

// ================= Stage A: head conv + decode =================
// BIT-EXACT reference model (confirmed R13):
//   obj: lane l partial = sum over chunks of UNFUSED w[c0+l]*x + w[c0+32+l]*x,
//        then shfl_down tree 16,8,4,2,1.
//   cls/reg: k-sequential FUSED FMA.
// This round: row padding (132) + float4 obj loads — addressing only.
__global__ __launch_bounds__(256) void head_kernel(
    const float* __restrict__ feat,
    const float* __restrict__ Wobj, const float* __restrict__ bobj,
    const float* __restrict__ Wcls, const float* __restrict__ bcls,
    const float* __restrict__ Wreg, const float* __restrict__ breg,
    int H, int W, float stride, int out_off)
{
    __shared__ __align__(16) float sm[85 * ROWF];   // 44.9 KB
    const int HW   = H * W;
    const int p0   = blockIdx.x * 128;
    const int tid  = threadIdx.x;
    const int wid  = tid >> 5;
    const int lane = tid & 31;
    const int nout = (92 - wid) / 8;

    float acc[11][4];
    #pragma unroll
    for (int j = 0; j < 11; j++)
        #pragma unroll
        for (int k = 0; k < 4; k++) acc[j][k] = 0.0f;

    float objp[16];
    #pragma unroll
    for (int q = 0; q < 16; q++) objp[q] = 0.0f;

    const float* wptr[11];
    #pragma unroll
    for (int j = 0; j < 11; j++) {
        int o = wid + 8 * j;
        if (o < 85)
            wptr[j] = (o == 0) ? Wobj : (o < 5 ? Wreg + (o - 1) * 256 : Wcls + (o - 5) * 256);
        else
            wptr[j] = Wobj;
    }

    for (int ch = 0; ch < 4; ch++) {
        int c0 = ch * 64;
        __syncthreads();
        for (int idx = tid; idx < 64 * 128; idx += 256) {
            int c = idx >> 7, p = idx & 127;
            int pg = p0 + p;
            sm[c * ROWF + p] = (pg < HW) ? feat[(size_t)(c0 + c) * HW + pg] : 0.0f;
        }
        __syncthreads();
        // ---- obj: per-lane stride-32 partials, unfused, c ascending (float4 loads) ----
        {
            float wl0 = Wobj[c0 + lane];
            float wl1 = Wobj[c0 + 32 + lane];
            int qbase = wid * 16;
            const float4* r0 = (const float4*)(sm + lane * ROWF + qbase);
            const float4* r1 = (const float4*)(sm + (lane + 32) * ROWF + qbase);
            #pragma unroll
            for (int t4 = 0; t4 < 4; t4++) {
                float4 xa = r0[t4];
                float4 xb = r1[t4];
                int q = t4 * 4;
                objp[q+0] = __fadd_rn(objp[q+0], __fmul_rn(wl0, xa.x));
                objp[q+0] = __fadd_rn(objp[q+0], __fmul_rn(wl1, xb.x));
                objp[q+1] = __fadd_rn(objp[q+1], __fmul_rn(wl0, xa.y));
                objp[q+1] = __fadd_rn(objp[q+1], __fmul_rn(wl1, xb.y));
                objp[q+2] = __fadd_rn(objp[q+2], __fmul_rn(wl0, xa.z));
                objp[q+2] = __fadd_rn(objp[q+2], __fmul_rn(wl1, xb.z));
                objp[q+3] = __fadd_rn(objp[q+3], __fmul_rn(wl0, xa.w));
                objp[q+3] = __fadd_rn(objp[q+3], __fmul_rn(wl1, xb.w));
            }
        }
        // ---- cls/reg: fused sequential-k ----
        #pragma unroll
        for (int j = 0; j < 11; j++) {
            if (j >= nout) break;
            if (j == 0 && wid == 0) continue;     // obj handled above
            const float* wp = wptr[j] + c0;
            float a0 = acc[j][0], a1 = acc[j][1], a2 = acc[j][2], a3 = acc[j][3];
            #pragma unroll
            for (int c = 0; c < 64; c += 4) {
                float4 wv = *(const float4*)(wp + c);
                float4 x0 = *(const float4*)(sm + (c + 0) * ROWF + lane * 4);
                float4 x1 = *(const float4*)(sm + (c + 1) * ROWF + lane * 4);
                float4 x2 = *(const float4*)(sm + (c + 2) * ROWF + lane * 4);
                float4 x3 = *(const float4*)(sm + (c + 3) * ROWF + lane * 4);
                a0 = __fmaf_rn(wv.x, x0.x, a0); a1 = __fmaf_rn(wv.x, x0.y, a1);
                a2 = __fmaf_rn(wv.x, x0.z, a2); a3 = __fmaf_rn(wv.x, x0.w, a3);
                a0 = __fmaf_rn(wv.y, x1.x, a0); a1 = __fmaf_rn(wv.y, x1.y, a1);
                a2 = __fmaf_rn(wv.y, x1.z, a2); a3 = __fmaf_rn(wv.y, x1.w, a3);
                a0 = __fmaf_rn(wv.z, x2.x, a0); a1 = __fmaf_rn(wv.z, x2.y, a1);
                a2 = __fmaf_rn(wv.z, x2.z, a2); a3 = __fmaf_rn(wv.z, x2.w, a3);
                a0 = __fmaf_rn(wv.w, x3.x, a0); a1 = __fmaf_rn(wv.w, x3.y, a1);
                a2 = __fmaf_rn(wv.w, x3.z, a2); a3 = __fmaf_rn(wv.w, x3.w, a3);
            }
            acc[j][0] = a0; acc[j][1] = a1; acc[j][2] = a2; acc[j][3] = a3;
        }
    }
    // ---- obj warp tree reduce: shfl_down 16,8,4,2,1 ----
    float objv[16];
    #pragma unroll
    for (int q = 0; q < 16; q++) {
        float v = objp[q];
        v = __fadd_rn(v, __shfl_down_sync(0xffffffffu, v, 16));
        v = __fadd_rn(v, __shfl_down_sync(0xffffffffu, v, 8));
        v = __fadd_rn(v, __shfl_down_sync(0xffffffffu, v, 4));
        v = __fadd_rn(v, __shfl_down_sync(0xffffffffu, v, 2));
        v = __fadd_rn(v, __shfl_down_sync(0xffffffffu, v, 1));
        objv[q] = v;
    }
    __syncthreads();
    #pragma unroll
    for (int j = 0; j < 11; j++) {
        if (j >= nout) break;
        int o = wid + 8 * j;
        if (o == 0) continue;
        float b = (o < 5) ? breg[o - 1] : bcls[o - 5];
        #pragma unroll
        for (int k = 0; k < 4; k++) sm[o * ROWF + lane * 4 + k] = __fadd_rn(acc[j][k], b);
    }
    if (lane == 0) {
        float b = bobj[0];
        #pragma unroll
        for (int q = 0; q < 16; q++)
            sm[0 * ROWF + wid * 16 + q] = __fadd_rn(objv[q], b);
    }
    __syncthreads();

    if (tid < 128) {
        int pg = p0 + tid;
        if (pg < HW) {
            float so = sigm(sm[0 * ROWF + tid]);
            float r0 = __fmul_rn(expf(sm[1 * ROWF + tid]), stride);
            float r1 = __fmul_rn(expf(sm[2 * ROWF + tid]), stride);
            float r2 = __fmul_rn(expf(sm[3 * ROWF + tid]), stride);
            float r3 = __fmul_rn(expf(sm[4 * ROWF + tid]), stride);
            float mx = -1.0f;
            int lab = 0;
            for (int c = 0; c < 80; c++) {
                float pc = __fmul_rn(so, sigm(sm[(5 + c) * ROWF + tid]));
                if (pc > mx) { mx = pc; lab = c; }
            }
            float ax = __fmul_rn(__fadd_rn((float)(pg % W), 0.5f), stride);
            float ay = __fmul_rn(__fadd_rn((float)(pg / W), 0.5f), stride);
            int gi = out_off + pg;
            g_score[gi] = mx;
            g_label[gi] = lab;
            g_box[gi * 4 + 0] = __fsub_rn(ax, r0);
            g_box[gi * 4 + 1] = __fsub_rn(ay, r1);
            g_box[gi * 4 + 2] = __fadd_rn(ax, r2);
            g_box[gi * 4 + 3] = __fadd_rn(ay, r3);
        }
    }
}

// ================= Stage B: per-level exact top-1000, stable low-first =================
// Warp-aggregated histogram + compaction (identical counts/set, fewer atomics).
__global__ __launch_bounds__(1024) void topk_kernel() {
    __shared__ unsigned int hist[256];
    __shared__ unsigned long long skeys[2048];
    __shared__ unsigned int s_prefix, s_K, s_cnt;

    const int loff[3] = {0, 25600, 32000};
    const int lnum[3] = {25600, 6400, 1600};
    int l = blockIdx.x;
    int off = loff[l], n = lnum[l];
    int tid = threadIdx.x;
    unsigned lane = tid & 31u;

    unsigned int prefix = 0;
    int K = KTOP;
    for (int pass = 0; pass < 4; pass++) {
        int shift = 24 - 8 * pass;
        if (tid < 256) hist[tid] = 0;
        __syncthreads();
        for (int i = tid; i < n; i += 1024) {
            unsigned int k = fflip(g_score[off + i]);
            bool ok = (pass == 0) || ((k >> (shift + 8)) == (prefix >> (shift + 8)));
            if (ok) {
                unsigned bucket = (k >> shift) & 255u;
                unsigned grp = __match_any_sync(__activemask(), bucket);
                int leader = __ffs(grp) - 1;
                if ((int)lane == leader) atomicAdd(&hist[bucket], (unsigned)__popc(grp));
            }
        }
        __syncthreads();
        if (tid == 0) {
            int cum = 0, b = 255;
            for (; b > 0; b--) {
                int h = (int)hist[b];
                if (cum + h >= K) break;
                cum += h;
            }
            s_prefix = prefix | ((unsigned int)b << shift);
            s_K = (unsigned int)(K - cum);
        }
        __syncthreads();
        prefix = s_prefix;
        K = (int)s_K;
        __syncthreads();
    }
    unsigned int T = prefix;

    if (tid == 0) s_cnt = 0;
    __syncthreads();
    for (int i = tid; i < n; i += 1024) {
        unsigned int k = fflip(g_score[off + i]);
        bool sel = (k >= T);
        unsigned am = __activemask();
        unsigned vote = __ballot_sync(am, sel);
        if (sel) {
            unsigned grp = vote;
            int leader = __ffs(grp) - 1;
            unsigned base = 0;
            if ((int)lane == leader) base = atomicAdd(&s_cnt, (unsigned)__popc(grp));
            base = __shfl_sync(grp, base, leader);
            unsigned p = base + (unsigned)__popc(grp & ((1u << lane) - 1u));
            if (p < 2048)
                skeys[p] = ((unsigned long long)k << 32) | (unsigned int)(~i);
        }
    }
    __syncthreads();
    unsigned int cnt = min(s_cnt, 2048u);
    for (int i = tid; i < 2048; i += 1024)
        if ((unsigned)i >= cnt) skeys[i] = 0ull;
    __syncthreads();

    for (int k2 = 2; k2 <= 2048; k2 <<= 1) {
        for (int j = k2 >> 1; j > 0; j >>= 1) {
            for (int idx = tid; idx < 2048; idx += 1024) {
                int ixj = idx ^ j;
                if (ixj > idx) {
                    unsigned long long a = skeys[idx], b = skeys[ixj];
                    bool desc = ((idx & k2) == 0);
                    if (desc ? (a < b) : (a > b)) { skeys[idx] = b; skeys[ixj] = a; }
                }
            }
            __syncthreads();
        }
    }

    for (int r = tid; r < KTOP; r += 1024) {
        unsigned long long key = skeys[r];
        int hw = (int)(~(unsigned int)key);
        int gi = off + hw;
        int ci = l * KTOP + r;
        c_score[ci] = g_score[gi];
        c_label[ci] = g_label[gi];
        #pragma unroll
        for (int k = 0; k < 4; k++) c_box[ci * 4 + k] = g_box[gi * 4 + k];
    }
}

// ================= Stage C: global argsort(-score), stable =================
__global__ __launch_bounds__(1024) void gsort_kernel() {
    __shared__ unsigned long long sk[4096];
    int tid = threadIdx.x;
    for (int i = tid; i < 4096; i += 1024)
        sk[i] = (i < NCAND)
              ? (((unsigned long long)fflip(c_score[i]) << 32) | (unsigned int)(~i))
              : 0ull;
    __syncthreads();
    for (int k2 = 2; k2 <= 4096; k2 <<= 1) {
        for (int j = k2 >> 1; j > 0; j >>= 1) {
            for (int idx = tid; idx < 4096; idx += 1024) {
                int ixj = idx ^ j;
                if (ixj > idx) {
                    unsigned long long a = sk[idx], b = sk[ixj];
                    bool desc = ((idx & k2) == 0);
                    if (desc ? (a < b) : (a > b)) { sk[idx] = b; sk[ixj] = a; }
                }
            }
            __syncthreads();
        }
    }
    for (int i = tid; i < NCAND; i += 1024) {
        int ci = (int)(~(unsigned int)sk[i]);
        g_order[i] = ci;
        float offv = __fmul_rn((float)c_label[ci], 8192.0f);
        #pragma unroll
        for (int k = 0; k < 4; k++)
            g_sbox[i * 4 + k] = __fadd_rn(c_box[ci * 4 + k], offv);
        g_valid[i] = (c_score[ci] >= 0.05f) ? 1 : 0;
    }
}

// ================= Stage D1: IoU bitmask (256-thread blocks) =================
__global__ __launch_bounds__(256) void nms_mask_kernel() {
    __shared__ float4 bj[64];
    __shared__ float  aj[64];
    int t = threadIdx.x;
    int jb = blockIdx.y * 64;
    if (t < 64) {
        int j = jb + t;
        if (j < NCAND) {
            float4 b = *(const float4*)&g_sbox[j * 4];
            bj[t] = b;
            aj[t] = __fmul_rn(__fsub_rn(b.z, b.x), __fsub_rn(b.w, b.y));
        }
    }
    __syncthreads();
    int i = blockIdx.x * 256 + t;
    if (i >= NCAND) return;
    float4 a = *(const float4*)&g_sbox[i * 4];
    float areai = __fmul_rn(__fsub_rn(a.z, a.x), __fsub_rn(a.w, a.y));
    unsigned long long bits = 0ull;
    int jn = min(64, NCAND - jb);
    for (int jj = 0; jj < jn; jj++) {
        float4 b = bj[jj];
        float xx1 = fmaxf(a.x, b.x), yy1 = fmaxf(a.y, b.y);
        float xx2 = fminf(a.z, b.z), yy2 = fminf(a.w, b.w);
        float w = fmaxf(1e-10f, __fsub_rn(xx2, xx1));
        float h = fmaxf(1e-10f, __fsub_rn(yy2, yy1));
        float inter = __fmul_rn(w, h);
        float denom = __fadd_rn(__fsub_rn(__fadd_rn(areai, aj[jj]), inter), 1e-14f);
        float iou = __fdiv_rn(inter, denom);
        if (iou > 0.6f) bits |= (1ull << jj);
    }
    g_mask[(size_t)i * NWORDS + blockIdx.y] = bits;
}

// ================= Stage D2: exact greedy pass, double-buffered =================
__global__ __launch_bounds__(256) void nms_seq_kernel() {
    __shared__ unsigned long long remv[NWORDS];
    __shared__ unsigned long long srows[2][64 * NWORDS];
    __shared__ unsigned char skp[64];
    __shared__ unsigned char svalid[2][64];
    int tid = threadIdx.x;
    if (tid < NWORDS) remv[tid] = 0ull;

    // preload group 0 into buffer 0
    for (int idx = tid; idx < 64 * NWORDS; idx += 256)
        srows[0][idx] = g_mask[idx];
    if (tid < 64) svalid[0][tid] = (unsigned char)g_valid[tid];
    __syncthreads();

    for (int g = 0; g < NWORDS; g++) {
        int cur = g & 1, nxt = cur ^ 1;
        int ib = g * 64;
        int cnt = min(64, NCAND - ib);
        if (tid == 0) {
            // serial greedy over group g (register chain; rows prefetched)
            unsigned long long r = remv[g];
            unsigned long long nextrow = srows[cur][g];
            for (int li = 0; li < cnt; li++) {
                unsigned long long row = nextrow;
                if (li + 1 < cnt) nextrow = srows[cur][(li + 1) * NWORDS + g];
                bool kp = svalid[cur][li] && !((r >> li) & 1ull);
                skp[li] = kp ? 1 : 0;
                if (kp) r |= row;
            }
            remv[g] = r;
        } else if (g + 1 < NWORDS) {
            // overlap: load group g+1 into the other buffer
            int ib2 = (g + 1) * 64;
            int cnt2 = min(64, NCAND - ib2);
            for (int idx = tid - 1; idx < cnt2 * NWORDS; idx += 255)
                srows[nxt][idx] = g_mask[(size_t)ib2 * NWORDS + idx];
            if (tid >= 192 && tid - 192 < cnt2)
                svalid[nxt][tid - 192] = (unsigned char)g_valid[ib2 + tid - 192];
        }
        __syncthreads();
        // bulk cross-group suppression OR
        for (int t = tid; t < NWORDS * 4; t += 256) {
            int w = t % NWORDS, part = t / NWORDS;
            unsigned long long acc = 0ull;
            for (int li = part; li < cnt; li += 4)
                if (skp[li]) acc |= srows[cur][li * NWORDS + w];
            if (acc) atomicOr(&remv[w], acc);
        }
        if (tid < cnt) g_keep[g_order[ib + tid]] = skp[tid];
        __syncthreads();
    }
}

// ================= Stage E: write packed output =================
__global__ __launch_bounds__(256) void output_kernel(float* __restrict__ out, int out_size) {
    int i = blockIdx.x * 256 + threadIdx.x;
    if (i >= NCAND) return;
    #pragma unroll
    for (int k = 0; k < 4; k++) {
        int oi = i * 4 + k;
        if (oi < out_size) {
            float v = __fdiv_rn(c_box[i * 4 + k], 1280.0f);
            out[oi] = fminf(fmaxf(v, 0.0f), 1.0f);
        }
    }
    if (12000 + i < out_size) out[12000 + i] = c_score[i];
    if (15000 + i < out_size) out[15000 + i] = (float)c_label[i];
    if (18000 + i < out_size) out[18000 + i] = g_keep[i] ? 1.0f : 0.0f;
}

// ================= launch =================
extern "C" void kernel_launch(void* const* d_in, const int* in_sizes, int n_in,
                              void* d_out, int out_size) {
    (void)n_in;
    bool sig = (in_sizes[1] > 100000);
    const float *feat[3], *Wo[3], *bo[3], *Wc[3], *bc[3], *Wr[3], *br[3];
    for (int l = 0; l < 3; l++) {
        if (sig) {
            feat[l] = (const float*)d_in[l];
            Wo[l] = (const float*)d_in[3 + 6 * l + 0];
            bo[l] = (const float*)d_in[3 + 6 * l + 1];
            Wc[l] = (const float*)d_in[3 + 6 * l + 2];
            bc[l] = (const float*)d_in[3 + 6 * l + 3];
            Wr[l] = (const float*)d_in[3 + 6 * l + 4];
            br[l] = (const float*)d_in[3 + 6 * l + 5];
        } else {
            feat[l] = (const float*)d_in[7 * l + 0];
            Wo[l] = (const float*)d_in[7 * l + 1];
            bo[l] = (const float*)d_in[7 * l + 2];
            Wc[l] = (const float*)d_in[7 * l + 3];
            bc[l] = (const float*)d_in[7 * l + 4];
            Wr[l] = (const float*)d_in[7 * l + 5];
            br[l] = (const float*)d_in[7 * l + 6];
        }
    }
    const int   Hs[3]  = {160, 80, 40};
    const int   Ws[3]  = {160, 80, 40};
    const float st[3]  = {8.0f, 16.0f, 32.0f};
    const int   off[3] = {0, 25600, 32000};

    for (int l = 0; l < 3; l++) {
        int HW = Hs[l] * Ws[l];
        int nb = (HW + 127) / 128;
        head_kernel<<<nb, 256>>>(feat[l], Wo[l], bo[l], Wc[l], bc[l], Wr[l], br[l],
                                 Hs[l], Ws[l], st[l], off[l]);
    }
    topk_kernel<<<3, 1024>>>();
    gsort_kernel<<<1, 1024>>>();
    nms_mask_kernel<<<dim3((NCAND + 255) / 256, NWORDS), 256>>>();
    nms_seq_kernel<<<1, 256>>>();
    output_kernel<<<(NCAND + 255) / 256, 256>>>((float*)d_out, out_size);
}